// round 5
// baseline (speedup 1.0000x reference)
#include <cuda_runtime.h>
#include <cstdint>

#define BATCH 8
#define NPTS  8192
#define NS    2048
#define KNBR  32
#define TB    512
#define NFPS  (2 * BATCH)      // 16 FPS CTAs (2 per batch, clustered)
#define HALF  (NPTS / 2)       // 4096 points per FPS CTA
#define PPT   (HALF / TB)      // 8 points per thread
#define NPAIR (PPT / 2)        // 4 packed pairs
#define NWARP (TB / 32)        // 16

// scratch
__device__ float    g_new_xyz[BATCH * NS * 3];
__device__ unsigned g_progress[BATCH];

__device__ __forceinline__ unsigned ld_acq(const unsigned* p) {
    unsigned v;
    asm volatile("ld.acquire.gpu.global.u32 %0, [%1];" : "=r"(v) : "l"(p) : "memory");
    return v;
}
__device__ __forceinline__ void st_rel(unsigned* p, unsigned v) {
    asm volatile("st.release.gpu.global.u32 [%0], %1;" :: "l"(p), "r"(v) : "memory");
}

// packed f32x2 helpers (two independent IEEE f32 ops per instruction)
__device__ __forceinline__ unsigned long long pk2(float lo, float hi) {
    unsigned long long r;
    asm("mov.b64 %0, {%1, %2};" : "=l"(r) : "f"(lo), "f"(hi));
    return r;
}
__device__ __forceinline__ void upk2(float& lo, float& hi, unsigned long long v) {
    asm("mov.b64 {%0, %1}, %2;" : "=f"(lo), "=f"(hi) : "l"(v));
}
__device__ __forceinline__ unsigned long long add2(unsigned long long a, unsigned long long b) {
    unsigned long long r;
    asm("add.rn.f32x2 %0, %1, %2;" : "=l"(r) : "l"(a), "l"(b));
    return r;
}
__device__ __forceinline__ unsigned long long mul2(unsigned long long a, unsigned long long b) {
    unsigned long long r;
    asm("mul.rn.f32x2 %0, %1, %2;" : "=l"(r) : "l"(a), "l"(b));
    return r;
}

// --- cluster / DSMEM helpers ---
__device__ __forceinline__ uint32_t smem_u32(const void* p) {
    uint32_t a;
    asm("{ .reg .u64 t; cvta.to.shared.u64 t, %1; cvt.u32.u64 %0, t; }"
        : "=r"(a) : "l"(p));
    return a;
}
__device__ __forceinline__ uint32_t ctarank() {
    uint32_t r;
    asm("mov.u32 %0, %%cluster_ctarank;" : "=r"(r));
    return r;
}
__device__ __forceinline__ uint32_t mapa_u32(uint32_t addr, uint32_t rank) {
    uint32_t r;
    asm("mapa.shared::cluster.u32 %0, %1, %2;" : "=r"(r) : "r"(addr), "r"(rank));
    return r;
}
__device__ __forceinline__ void st_remote_u64(uint32_t addr, unsigned long long v) {
    asm volatile("st.shared::cluster.u64 [%0], %1;" :: "r"(addr), "l"(v) : "memory");
}
__device__ __forceinline__ void sts_u64(uint32_t addr, unsigned long long v) {
    asm volatile("st.shared.u64 [%0], %1;" :: "r"(addr), "l"(v) : "memory");
}
__device__ __forceinline__ unsigned long long lds_u64(uint32_t addr) {
    unsigned long long v;
    asm volatile("ld.shared.u64 %0, [%1];" : "=l"(v) : "r"(addr));
    return v;
}
__device__ __forceinline__ void mbar_init(uint32_t addr, uint32_t count) {
    asm volatile("mbarrier.init.shared.b64 [%0], %1;" :: "r"(addr), "r"(count) : "memory");
}
__device__ __forceinline__ void mbar_arrive_local(uint32_t addr) {
    asm volatile("mbarrier.arrive.release.cta.shared::cta.b64 _, [%0];" :: "r"(addr) : "memory");
}
__device__ __forceinline__ void mbar_arrive_remote(uint32_t addr) {
    asm volatile("mbarrier.arrive.release.cluster.shared::cluster.b64 _, [%0];" :: "r"(addr) : "memory");
}
__device__ __forceinline__ void mbar_wait_cluster(uint32_t addr, uint32_t parity) {
    uint32_t done;
    do {
        asm volatile(
            "{\n\t.reg .pred p;\n\t"
            "mbarrier.try_wait.parity.acquire.cluster.shared::cta.b64 p, [%1], %2, 0x989680;\n\t"
            "selp.b32 %0, 1, 0, p;\n\t}"
            : "=r"(done) : "r"(addr), "r"(parity) : "memory");
    } while (!done);
}

extern "C" __global__ void reset_kernel() {
    if (threadIdx.x < BATCH) g_progress[threadIdx.x] = 0;
}

// ---------------------------------------------------------------------------
// Fused kernel, cluster_dims = 2.
// Blocks 0..15: FPS producer pairs (blocks 2b, 2b+1 -> batch b).
// Blocks 16.. : 16 warps, one centroid each: ball query + MLP + max pool.
// ---------------------------------------------------------------------------
extern "C" __global__ void __launch_bounds__(TB, 1) __cluster_dims__(2, 1, 1)
fused_kernel(const float* __restrict__ xyz,
             const float* __restrict__ w1, const float* __restrict__ b1,
             const float* __restrict__ w2, const float* __restrict__ b2,
             const float* __restrict__ w3, const float* __restrict__ b3,
             float* __restrict__ out)
{
    extern __shared__ float sm[];
    const int t    = threadIdx.x;
    const int lane = t & 31;
    const int w    = t >> 5;

    if (blockIdx.x < NFPS) {
        // ================= FPS producer (2-CTA cluster per batch) ==========
        // slots[par][0..15]  = this CTA's per-warp winners
        // slots[par][16..31] = peer CTA's per-warp winners (written via DSMEM)
        // key = (float_bits(dd) << 32) | (u32)~idx   (dd>=0 -> bits ordered;
        // tie -> umax(~idx) = min idx, matching jnp.argmax)
        __shared__ unsigned long long slots[2][32];
        __shared__ unsigned long long mbar;

        float* sx = sm;
        float* sy = sm + NPTS;
        float* sz = sm + 2 * NPTS;

        const int b = blockIdx.x >> 1;
        const uint32_t rank  = ctarank();
        const uint32_t peer  = rank ^ 1u;
        const int      pbase = (int)rank * HALF;
        const float* base = xyz + (size_t)b * NPTS * 3;

        const uint32_t mbar_l   = smem_u32(&mbar);
        const uint32_t slots_l  = smem_u32(&slots[0][0]);
        const uint32_t mbar_r   = mapa_u32(mbar_l, peer);
        const uint32_t slots_r  = mapa_u32(slots_l, peer);

        if (t == 0) mbar_init(mbar_l, 32);

        // full point cloud in smem (both CTAs need all coords for centroid lookup)
#pragma unroll
        for (int i = 0; i < NPTS / TB; i++) {
            int idx = t + i * TB;
            sx[idx] = base[idx * 3 + 0];
            sy[idx] = base[idx * 3 + 1];
            sz[idx] = base[idx * 3 + 2];
        }
        __syncthreads();
        // mbarrier + smem visible cluster-wide before any remote traffic
        asm volatile("barrier.cluster.arrive.aligned;" ::: "memory");
        asm volatile("barrier.cluster.wait.aligned;" ::: "memory");

        // register-resident half: pair p = points pbase + t + (2p)*TB / (2p+1)*TB
        unsigned long long px2[NPAIR], py2[NPAIR], pz2[NPAIR];
        float dd[PPT];
#pragma unroll
        for (int p = 0; p < NPAIR; p++) {
            int i0 = pbase + t + (2 * p) * TB;
            int i1 = pbase + t + (2 * p + 1) * TB;
            px2[p] = pk2(sx[i0], sx[i1]);
            py2[p] = pk2(sy[i0], sy[i1]);
            pz2[p] = pk2(sz[i0], sz[i1]);
        }
#pragma unroll
        for (int i = 0; i < PPT; i++) dd[i] = 1e10f;

        int far = 0;
        float* out_xyz = out + (size_t)b * 3 * NS;
        float* gx      = g_new_xyz + (size_t)b * NS * 3;

        for (int s = 0; s < NS; s++) {
            const int par = s & 1;
            float cx = sx[far], cy = sy[far], cz = sz[far];
            if (rank == 0 && t == 0) {
                out_xyz[0 * NS + s] = cx;
                out_xyz[1 * NS + s] = cy;
                out_xyz[2 * NS + s] = cz;
                gx[s * 3 + 0] = cx; gx[s * 3 + 1] = cy; gx[s * 3 + 2] = cz;
                if ((s & 15) == 15) st_rel(&g_progress[b], (unsigned)(s + 1));
            }
            // negation exact: a + (-c) == a - c
            unsigned long long ncx = pk2(-cx, -cx);
            unsigned long long ncy = pk2(-cy, -cy);
            unsigned long long ncz = pk2(-cz, -cz);

            float bv   = -1.0f;
            int   slot = 0;
#pragma unroll
            for (int p = 0; p < NPAIR; p++) {
                unsigned long long dx = add2(px2[p], ncx);
                unsigned long long dy = add2(py2[p], ncy);
                unsigned long long dz = add2(pz2[p], ncz);
                dx = mul2(dx, dx);
                dy = mul2(dy, dy);
                dz = mul2(dz, dz);
                unsigned long long d2 = add2(add2(dx, dy), dz);  // (x2+y2)+z2
                float dlo, dhi;
                upk2(dlo, dhi, d2);
                float n0 = fminf(dd[2 * p + 0], dlo); dd[2 * p + 0] = n0;
                float n1 = fminf(dd[2 * p + 1], dhi); dd[2 * p + 1] = n1;
                // ascending slot within thread: strict > keeps lowest index
                if (n0 > bv) { bv = n0; slot = 2 * p + 0; }
                if (n1 > bv) { bv = n1; slot = 2 * p + 1; }
            }
            int bi = pbase + t + slot * TB;
            // warp argmax via REDUX (exact lowest-index tie-break)
            int fb = __float_as_int(bv);   // dd >= 0 -> nonneg bits after iter math
            int mb = __reduce_max_sync(0xffffffffu, fb);
            int ca = (fb == mb) ? bi : 0x7fffffff;
            int wi = __reduce_min_sync(0xffffffffu, ca);
            if (lane == 0) {
                unsigned long long key =
                    ((unsigned long long)(unsigned)mb << 32) | (unsigned)(~wi);
                uint32_t off_own  = (uint32_t)((par * 32 + w) * 8);
                uint32_t off_peer = (uint32_t)((par * 32 + 16 + w) * 8);
                sts_u64(slots_l + off_own, key);
                st_remote_u64(slots_r + off_peer, key);
                mbar_arrive_local(mbar_l);
                mbar_arrive_remote(mbar_r);
            }
            mbar_wait_cluster(mbar_l, (uint32_t)par);
            // every warp combines all 32 winners (16 local + 16 peer)
            unsigned long long k = lds_u64(slots_l + (uint32_t)((par * 32 + lane) * 8));
            int      hi = (int)(k >> 32);
            unsigned lo = (unsigned)k;
            int m2 = __reduce_max_sync(0xffffffffu, hi);
            unsigned cand = (hi == m2) ? lo : 0u;
            unsigned mi = __reduce_max_sync(0xffffffffu, cand);
            far = (int)(~mi);
        }
        if (rank == 0 && t == 0) st_rel(&g_progress[b], (unsigned)NS);
    } else {
        // ================= MLP consumer =================
        float* w1s = sm;              // 64x3
        float* b1s = w1s + 192;       // 64
        float* w2t = b1s + 64;        // 64x64 transposed [c][o]
        float* b2s = w2t + 4096;      // 64
        float* w3s = b2s + 64;        // 128x64 row-major [o][c]
        float* b3s = w3s + 8192;      // 128
        int*   lists = (int*)(b3s + 128);  // NWARP * 32

        for (int i = t; i < 192; i += TB) w1s[i] = w1[i];
        if (t < 64) { b1s[t] = b1[t]; b2s[t] = b2[t]; }
        for (int i = t; i < 4096; i += TB) {
            int o = i >> 6, c = i & 63;
            w2t[c * 64 + o] = w2[i];
        }
        for (int i = t; i < 8192; i += TB) w3s[i] = w3[i];
        if (t < 128) b3s[t] = b3[t];

        // block mapping: batch b, s range [sbase, sbase+16)
        const int idx   = blockIdx.x - NFPS;       // 0..1023
        const int b     = idx & 7;
        const int sbase = (idx >> 3) * NWARP;
        const int s     = sbase + w;

        // single poller per block, coarse gate on the whole block's range
        if (t == 0) {
            unsigned need = (unsigned)(sbase + NWARP);
            while (ld_acq(&g_progress[b]) < need) __nanosleep(2048);
        }
        __syncthreads();

        const float* xb   = xyz + (size_t)b * NPTS * 3;
        const float* cptr = g_new_xyz + ((size_t)b * NS + s) * 3;
        const float cx = cptr[0], cy = cptr[1], cz = cptr[2];

        // --- ball query: first KNBR points (ascending idx) with d2 <= r^2 ---
        int* list = lists + w * KNBR;
        int  cnt  = 0;
        for (int basei = 0; basei < NPTS; basei += 32) {
            int pi = basei + lane;
            float x = xb[pi * 3 + 0];
            float y = xb[pi * 3 + 1];
            float z = xb[pi * 3 + 2];
            float dx = __fsub_rn(x, cx);
            float dy = __fsub_rn(y, cy);
            float dz = __fsub_rn(z, cz);
            float d  = __fadd_rn(__fadd_rn(__fmul_rn(dx, dx), __fmul_rn(dy, dy)),
                                 __fmul_rn(dz, dz));
            bool within = (d <= 0.04f);
            unsigned m  = __ballot_sync(0xffffffffu, within);
            if (within) {
                int pos = cnt + __popc(m & ((1u << lane) - 1u));
                if (pos < KNBR) list[pos] = pi;
            }
            cnt += __popc(m);
            if (cnt >= KNBR) break;
        }
        __syncwarp();
        const int nb = list[(lane < cnt) ? lane : 0];

        const float rx = xb[nb * 3 + 0] - cx;
        const float ry = xb[nb * 3 + 1] - cy;
        const float rz = xb[nb * 3 + 2] - cz;

        // --- layer1 fused into layer2 accumulation ---
        float h2[64];
#pragma unroll
        for (int o = 0; o < 64; o++) h2[o] = b2s[o];

        for (int c = 0; c < 64; c++) {
            float a = fmaf(rx, w1s[c * 3 + 0], b1s[c]);
            a = fmaf(ry, w1s[c * 3 + 1], a);
            a = fmaf(rz, w1s[c * 3 + 2], a);
            float hv = fmaxf(a, 0.0f);
            const float4* row = (const float4*)(w2t + c * 64);
#pragma unroll
            for (int o4 = 0; o4 < 16; o4++) {
                float4 wv = row[o4];
                h2[o4 * 4 + 0] = fmaf(hv, wv.x, h2[o4 * 4 + 0]);
                h2[o4 * 4 + 1] = fmaf(hv, wv.y, h2[o4 * 4 + 1]);
                h2[o4 * 4 + 2] = fmaf(hv, wv.z, h2[o4 * 4 + 2]);
                h2[o4 * 4 + 3] = fmaf(hv, wv.w, h2[o4 * 4 + 3]);
            }
        }
#pragma unroll
        for (int o = 0; o < 64; o++) h2[o] = fmaxf(h2[o], 0.0f);

        // --- layer3 + relu + warp max-pool ---
        float* outb = out + (size_t)BATCH * 3 * NS + (size_t)b * 128 * NS + s;
        for (int o = 0; o < 128; o++) {
            float a = b3s[o];
            const float4* row = (const float4*)(w3s + o * 64);
#pragma unroll
            for (int c4 = 0; c4 < 16; c4++) {
                float4 wv = row[c4];
                a = fmaf(h2[c4 * 4 + 0], wv.x, a);
                a = fmaf(h2[c4 * 4 + 1], wv.y, a);
                a = fmaf(h2[c4 * 4 + 2], wv.z, a);
                a = fmaf(h2[c4 * 4 + 3], wv.w, a);
            }
            a = fmaxf(a, 0.0f);
#pragma unroll
            for (int off = 16; off; off >>= 1)
                a = fmaxf(a, __shfl_xor_sync(0xffffffffu, a, off));
            if (lane == 0) outb[(size_t)o * NS] = a;
        }
    }
}

// ---------------------------------------------------------------------------
extern "C" void kernel_launch(void* const* d_in, const int* in_sizes, int n_in,
                              void* d_out, int out_size)
{
    const float* xyz = (const float*)d_in[0];
    const float* w1 = (const float*)d_in[2];
    const float* b1 = (const float*)d_in[3];
    const float* w2 = (const float*)d_in[4];
    const float* b2 = (const float*)d_in[5];
    const float* w3 = (const float*)d_in[6];
    const float* b3 = (const float*)d_in[7];

    float* out = (float*)d_out;

    const int smem = 3 * NPTS * sizeof(float);   // 96 KB
    cudaFuncSetAttribute(fused_kernel,
                         cudaFuncAttributeMaxDynamicSharedMemorySize, smem);

    const int nmlp = (BATCH * NS) / NWARP;       // 1024 consumer blocks
    reset_kernel<<<1, 32>>>();
    fused_kernel<<<NFPS + nmlp, TB, smem>>>(xyz, w1, b1, w2, b2, w3, b3, out);
}

// round 6
// speedup vs baseline: 1.2822x; 1.2822x over previous
#include <cuda_runtime.h>
#include <cstdint>

#define BATCH 8
#define NPTS  8192
#define NS    2048
#define KNBR  32
#define TB    512
#define NWARP (TB / 32)      // 16
#define NBKT  16             // x-slab buckets (one per FPS warp)
#define CAP   576            // slots per warp (bucket capacity incl. pads)
#define PPT   18             // CAP/32 points per thread
#define NPAIR (PPT / 2)      // 9 packed pairs

// scratch
__device__ float    g_new_xyz[BATCH * NS * 3];
__device__ unsigned g_progress[BATCH];

__device__ __forceinline__ unsigned ld_acq(const unsigned* p) {
    unsigned v;
    asm volatile("ld.acquire.gpu.global.u32 %0, [%1];" : "=r"(v) : "l"(p) : "memory");
    return v;
}
__device__ __forceinline__ void st_rel(unsigned* p, unsigned v) {
    asm volatile("st.release.gpu.global.u32 [%0], %1;" :: "l"(p), "r"(v) : "memory");
}

// packed f32x2 helpers (two independent IEEE f32 ops per instruction)
__device__ __forceinline__ unsigned long long pk2(float lo, float hi) {
    unsigned long long r;
    asm("mov.b64 %0, {%1, %2};" : "=l"(r) : "f"(lo), "f"(hi));
    return r;
}
__device__ __forceinline__ void upk2(float& lo, float& hi, unsigned long long v) {
    asm("mov.b64 {%0, %1}, %2;" : "=f"(lo), "=f"(hi) : "l"(v));
}
__device__ __forceinline__ unsigned long long add2(unsigned long long a, unsigned long long b) {
    unsigned long long r;
    asm("add.rn.f32x2 %0, %1, %2;" : "=l"(r) : "l"(a), "l"(b));
    return r;
}
__device__ __forceinline__ unsigned long long mul2(unsigned long long a, unsigned long long b) {
    unsigned long long r;
    asm("mul.rn.f32x2 %0, %1, %2;" : "=l"(r) : "l"(a), "l"(b));
    return r;
}

extern "C" __global__ void reset_kernel() {
    if (threadIdx.x < BATCH) g_progress[threadIdx.x] = 0;
}

// ---------------------------------------------------------------------------
// Fused kernel. Blocks 0..7: FPS producer (one per batch), warp-per-x-slab
// with exact skip pruning. Blocks 8..: warp-per-centroid ball query + MLP.
// ---------------------------------------------------------------------------
extern "C" __global__ void __launch_bounds__(TB, 1)
fused_kernel(const float* __restrict__ xyz,
             const float* __restrict__ w1, const float* __restrict__ b1,
             const float* __restrict__ w2, const float* __restrict__ b2,
             const float* __restrict__ w3, const float* __restrict__ b3,
             float* __restrict__ out)
{
    extern __shared__ float sm[];
    const int t    = threadIdx.x;
    const int lane = t & 31;
    const int w    = t >> 5;

    if (blockIdx.x < BATCH) {
        // ================= FPS producer =================
        __shared__ unsigned long long skey2[2][32];   // [parity][warp or pad]
        __shared__ int s_filled[NBKT];
        __shared__ int s_ovfcnt;

        float* sx   = sm;
        float* sy   = sm + NPTS;
        float* sz   = sm + 2 * NPTS;
        int*   perm = (int*)(sm + 3 * NPTS);          // NBKT*CAP = 9216 slots
        int*   ovf  = perm + NBKT * CAP;              // up to NPTS (worst case)

        const int b = blockIdx.x;
        const float* base = xyz + (size_t)b * NPTS * 3;

        if (t == 0) s_ovfcnt = 0;
        if (t < 64) {                                  // zero the pad slots
            int pp = t >> 5, ll = t & 31;
            if (ll >= NWARP) skey2[pp][ll] = 0ull;
        }

        // load coords
        for (int i = t; i < NPTS; i += TB) {
            sx[i] = base[i * 3 + 0];
            sy[i] = base[i * 3 + 1];
            sz[i] = base[i * 3 + 2];
        }
        __syncthreads();

        // ---- stable bucket scatter: warp 0, lane b owns bucket b ----
        if (w == 0 && lane < NBKT) {
            int cur = 0;
            for (int i = 0; i < NPTS; i++) {
                float x = sx[i];
                int bkt = (int)(x * 16.0f);
                bkt = (bkt > 15) ? 15 : bkt;
                if (bkt == lane) {
                    if (cur < CAP) perm[lane * CAP + cur] = i;
                    else { int o = atomicAdd(&s_ovfcnt, 1); ovf[o] = i; }
                    cur++;
                }
            }
            s_filled[lane] = (cur < CAP) ? cur : CAP;
        }
        __syncthreads();
        // overflow redistribution (statistically never runs)
        if (t == 0) {
            for (int j = 0; j < s_ovfcnt; j++) {
                for (int b2 = 0; b2 < NBKT; b2++) {
                    if (s_filled[b2] < CAP) {
                        perm[b2 * CAP + s_filled[b2]] = ovf[j];
                        s_filled[b2]++;
                        break;
                    }
                }
            }
        }
        __syncthreads();
        // pads: replicate the bucket's first point (same original index ->
        // argmax ties between pad and original resolve identically)
        if (w == 0 && lane < NBKT) {
            int f = s_filled[lane];
            int rep = (f > 0) ? perm[lane * CAP] : 0;
            for (; f < CAP; f++) perm[lane * CAP + f] = rep;
        }
        __syncthreads();

        // ---- per-warp register load + x-bounds ----
        float fx[PPT], fy[PPT], fz[PPT], dd[PPT];
#pragma unroll
        for (int k = 0; k < PPT; k++) {
            int oi = perm[w * CAP + k * 32 + lane];
            fx[k] = sx[oi]; fy[k] = sy[oi]; fz[k] = sz[oi];
            dd[k] = 1e10f;
        }
        unsigned long long px2[NPAIR], py2[NPAIR], pz2[NPAIR];
#pragma unroll
        for (int p = 0; p < NPAIR; p++) {
            px2[p] = pk2(fx[2 * p], fx[2 * p + 1]);
            py2[p] = pk2(fy[2 * p], fy[2 * p + 1]);
            pz2[p] = pk2(fz[2 * p], fz[2 * p + 1]);
        }
        float mnx = fx[0], mxx = fx[0];
#pragma unroll
        for (int k = 1; k < PPT; k++) {
            mnx = fminf(mnx, fx[k]);
            mxx = fmaxf(mxx, fx[k]);
        }
        // coords >= 0 -> float bits are order-preserving as ints
        float xlo = __int_as_float(__reduce_min_sync(0xffffffffu, __float_as_int(mnx)));
        float xhi = __int_as_float(__reduce_max_sync(0xffffffffu, __float_as_int(mxx)));

        int mb = __float_as_int(1e10f);   // cached warp-max (forces active at s=0)
        int wi = 0;                       // cached warp argmax (original idx)
        int far = 0;
        float* out_xyz = out + (size_t)b * 3 * NS;
        float* gx      = g_new_xyz + (size_t)b * NS * 3;

        for (int s = 0; s < NS; s++) {
            const int par = s & 1;
            float cx = sx[far], cy = sy[far], cz = sz[far];
            if (t == 0) {
                out_xyz[0 * NS + s] = cx;
                out_xyz[1 * NS + s] = cy;
                out_xyz[2 * NS + s] = cz;
                gx[s * 3 + 0] = cx; gx[s * 3 + 1] = cy; gx[s * 3 + 2] = cz;
                if ((s & 15) == 15) st_rel(&g_progress[b], (unsigned)(s + 1));
            }

            // exact skip: if min x-distance to slab (with margin) exceeds the
            // warp's current max dd, no point's dd can change this iteration.
            float Bw  = __int_as_float(mb);
            float dxi = fmaxf(fmaxf(xlo - cx, cx - xhi), 0.0f);
            if (dxi * dxi <= Bw * 1.00001f) {
                // active: full distance update + argmax
                unsigned long long ncx = pk2(-cx, -cx);
                unsigned long long ncy = pk2(-cy, -cy);
                unsigned long long ncz = pk2(-cz, -cz);
                float bv   = -1.0f;
                int   slot = 0;
#pragma unroll
                for (int p = 0; p < NPAIR; p++) {
                    unsigned long long dx = add2(px2[p], ncx);
                    unsigned long long dy = add2(py2[p], ncy);
                    unsigned long long dz = add2(pz2[p], ncz);
                    dx = mul2(dx, dx);
                    dy = mul2(dy, dy);
                    dz = mul2(dz, dz);
                    unsigned long long d2 = add2(add2(dx, dy), dz); // (x2+y2)+z2
                    float dlo, dhi;
                    upk2(dlo, dhi, d2);
                    float n0 = fminf(dd[2 * p + 0], dlo); dd[2 * p + 0] = n0;
                    float n1 = fminf(dd[2 * p + 1], dhi); dd[2 * p + 1] = n1;
                    // ascending slot = ascending original idx (stable scatter):
                    // strict > keeps lowest original index on ties
                    if (n0 > bv) { bv = n0; slot = 2 * p + 0; }
                    if (n1 > bv) { bv = n1; slot = 2 * p + 1; }
                }
                int oidx = perm[w * CAP + slot * 32 + lane];
                int fb = __float_as_int(bv);
                mb = __reduce_max_sync(0xffffffffu, fb);
                int ca = (fb == mb) ? oidx : 0x7fffffff;
                wi = __reduce_min_sync(0xffffffffu, ca);
            }
            if (lane == 0) {
                skey2[par][w] =
                    ((unsigned long long)(unsigned)mb << 32) | (unsigned)(~wi);
            }
            __syncthreads();
            // combine all 16 warp winners (+16 zero pads) in every warp
            unsigned long long kk = skey2[par][lane];
            int      hi = (int)(kk >> 32);
            unsigned lo = (unsigned)kk;
            int m2 = __reduce_max_sync(0xffffffffu, hi);
            unsigned cand = (hi == m2) ? lo : 0u;
            unsigned mi = __reduce_max_sync(0xffffffffu, cand);
            far = (int)(~mi);
        }
        if (t == 0) st_rel(&g_progress[b], (unsigned)NS);
    } else {
        // ================= MLP consumer =================
        float* w1s = sm;              // 64x3
        float* b1s = w1s + 192;       // 64
        float* w2t = b1s + 64;        // 64x64 transposed [c][o]
        float* b2s = w2t + 4096;      // 64
        float* w3s = b2s + 64;        // 128x64 row-major [o][c]
        float* b3s = w3s + 8192;      // 128
        int*   lists = (int*)(b3s + 128);  // NWARP * 32

        for (int i = t; i < 192; i += TB) w1s[i] = w1[i];
        if (t < 64) { b1s[t] = b1[t]; b2s[t] = b2[t]; }
        for (int i = t; i < 4096; i += TB) {
            int o = i >> 6, c = i & 63;
            w2t[c * 64 + o] = w2[i];
        }
        for (int i = t; i < 8192; i += TB) w3s[i] = w3[i];
        if (t < 128) b3s[t] = b3[t];

        // block mapping: batch b, s range [sbase, sbase+16)
        const int idx   = blockIdx.x - BATCH;      // 0..1023
        const int b     = idx & 7;
        const int sbase = (idx >> 3) * NWARP;
        const int s     = sbase + w;

        // single poller per block, coarse gate on the whole block's range
        if (t == 0) {
            unsigned need = (unsigned)(sbase + NWARP);
            while (ld_acq(&g_progress[b]) < need) __nanosleep(2048);
        }
        __syncthreads();

        const float* xb   = xyz + (size_t)b * NPTS * 3;
        const float* cptr = g_new_xyz + ((size_t)b * NS + s) * 3;
        const float cx = cptr[0], cy = cptr[1], cz = cptr[2];

        // --- ball query: first KNBR points (ascending idx) with d2 <= r^2 ---
        int* list = lists + w * KNBR;
        int  cnt  = 0;
        for (int basei = 0; basei < NPTS; basei += 32) {
            int pi = basei + lane;
            float x = xb[pi * 3 + 0];
            float y = xb[pi * 3 + 1];
            float z = xb[pi * 3 + 2];
            float dx = __fsub_rn(x, cx);
            float dy = __fsub_rn(y, cy);
            float dz = __fsub_rn(z, cz);
            float d  = __fadd_rn(__fadd_rn(__fmul_rn(dx, dx), __fmul_rn(dy, dy)),
                                 __fmul_rn(dz, dz));
            bool within = (d <= 0.04f);
            unsigned m  = __ballot_sync(0xffffffffu, within);
            if (within) {
                int pos = cnt + __popc(m & ((1u << lane) - 1u));
                if (pos < KNBR) list[pos] = pi;
            }
            cnt += __popc(m);
            if (cnt >= KNBR) break;
        }
        __syncwarp();
        const int nb = list[(lane < cnt) ? lane : 0];

        const float rx = xb[nb * 3 + 0] - cx;
        const float ry = xb[nb * 3 + 1] - cy;
        const float rz = xb[nb * 3 + 2] - cz;

        // --- layer1 fused into layer2 accumulation ---
        float h2[64];
#pragma unroll
        for (int o = 0; o < 64; o++) h2[o] = b2s[o];

        for (int c = 0; c < 64; c++) {
            float a = fmaf(rx, w1s[c * 3 + 0], b1s[c]);
            a = fmaf(ry, w1s[c * 3 + 1], a);
            a = fmaf(rz, w1s[c * 3 + 2], a);
            float hv = fmaxf(a, 0.0f);
            const float4* row = (const float4*)(w2t + c * 64);
#pragma unroll
            for (int o4 = 0; o4 < 16; o4++) {
                float4 wv = row[o4];
                h2[o4 * 4 + 0] = fmaf(hv, wv.x, h2[o4 * 4 + 0]);
                h2[o4 * 4 + 1] = fmaf(hv, wv.y, h2[o4 * 4 + 1]);
                h2[o4 * 4 + 2] = fmaf(hv, wv.z, h2[o4 * 4 + 2]);
                h2[o4 * 4 + 3] = fmaf(hv, wv.w, h2[o4 * 4 + 3]);
            }
        }
#pragma unroll
        for (int o = 0; o < 64; o++) h2[o] = fmaxf(h2[o], 0.0f);

        // --- layer3 + relu + warp max-pool ---
        float* outb = out + (size_t)BATCH * 3 * NS + (size_t)b * 128 * NS + s;
        for (int o = 0; o < 128; o++) {
            float a = b3s[o];
            const float4* row = (const float4*)(w3s + o * 64);
#pragma unroll
            for (int c4 = 0; c4 < 16; c4++) {
                float4 wv = row[c4];
                a = fmaf(h2[c4 * 4 + 0], wv.x, a);
                a = fmaf(h2[c4 * 4 + 1], wv.y, a);
                a = fmaf(h2[c4 * 4 + 2], wv.z, a);
                a = fmaf(h2[c4 * 4 + 3], wv.w, a);
            }
            a = fmaxf(a, 0.0f);
#pragma unroll
            for (int off = 16; off; off >>= 1)
                a = fmaxf(a, __shfl_xor_sync(0xffffffffu, a, off));
            if (lane == 0) outb[(size_t)o * NS] = a;
        }
    }
}

// ---------------------------------------------------------------------------
extern "C" void kernel_launch(void* const* d_in, const int* in_sizes, int n_in,
                              void* d_out, int out_size)
{
    const float* xyz = (const float*)d_in[0];
    const float* w1 = (const float*)d_in[2];
    const float* b1 = (const float*)d_in[3];
    const float* w2 = (const float*)d_in[4];
    const float* b2 = (const float*)d_in[5];
    const float* w3 = (const float*)d_in[6];
    const float* b3 = (const float*)d_in[7];

    float* out = (float*)d_out;

    // FPS layout: coords 96KB + perm 36KB + ovf 32KB
    const int smem = 3 * NPTS * (int)sizeof(float)
                   + (NBKT * CAP) * (int)sizeof(int)
                   + NPTS * (int)sizeof(int) + 256;
    cudaFuncSetAttribute(fused_kernel,
                         cudaFuncAttributeMaxDynamicSharedMemorySize, smem);

    const int nmlp = (BATCH * NS) / NWARP;       // 1024 consumer blocks
    reset_kernel<<<1, 32>>>();
    fused_kernel<<<BATCH + nmlp, TB, smem>>>(xyz, w1, b1, w2, b2, w3, b3, out);
}